// round 11
// baseline (speedup 1.0000x reference)
#include <cuda_runtime.h>
#include <cstdint>

// Problem constants (fixed by setup_inputs)
#define B_ 16
#define A_ 9
#define H_ 128
#define W_ 128
#define S_ 2048.0f
// sigmoid(d) > 0.7  <=>  d > ln(7/3)
#define LOGIT_THRESH 0.84729786038720363f

#define TPB 128
#define WARP_BYTES (32 * 9 * 16)   // 4608 B contiguous output per warp

// Precomputed anchor table, (a, w) order: (acx, acy, aw, ah). 18 KB, L1/L2-hot.
// (per-block a*w*129 gather is lane-divergent: costs ~9us, measured R4 vs R5)
__device__ float4 d_anc_tab[A_ * W_];

__global__ void build_anchor_tab(const float* __restrict__ anchor) {
    int t = blockIdx.x * blockDim.x + threadIdx.x;
    if (t >= A_ * W_) return;
    int a = t / W_;
    int w = t % W_;
    long row = (long)a * w * (W_ + 1);    // idx[a,w] = a*w*(W+1)
    const float* p = anchor + row * 6;
    d_anc_tab[t] = make_float4(p[2], p[3], p[4], p[5]);
}

__device__ __forceinline__ uint32_t smem_u32(const void* p) {
    uint32_t a;
    asm("{ .reg .u64 t; cvta.to.shared.u64 t, %1; cvt.u32.u64 %0, t; }"
        : "=r"(a) : "l"(p));
    return a;
}

// R9 structure, but per-WARP TMA stores: no block barrier. Each warp packs its
// 4608B contiguous smem region, syncwarps, lane 0 fences + issues the bulk
// store, and only waits (read-drain) at kernel end. Fast warps stream out
// early; their drain overlaps the other warps' compute.
__global__ __launch_bounds__(TPB) void proposal_kernel(
    const float* __restrict__ cla,
    const float* __restrict__ reg,
    float* __restrict__ out)
{
    // TPB threads x 9 float4 slots, output-linear layout. Warp w owns the
    // contiguous slice [32w*9, 32(w+1)*9).
    __shared__ __align__(128) float4 sOut[TPB * 9];   // 18432 B

    const int WQ  = W_ / 4;         // 32
    const int HW4 = (H_ * W_) / 4;  // 4096 float4 per channel plane

    int tid = threadIdx.x;
    int t = blockIdx.x * TPB + tid;
    int wq = t & (WQ - 1);                    // == tid & 31
    int h  = (t / WQ) & (H_ - 1);
    int a  = (t / (WQ * H_)) % A_;            // uniform within a block
    int b  =  t / (WQ * H_ * A_);
    int w0 = wq * 4;

    int sp4 = (h * W_ + w0) >> 2;

    const float4* cla4 = (const float4*)cla;
    const float4* reg4 = (const float4*)reg;

    int cbase = (b * 2 * A_ + 2 * a) * HW4 + sp4;
    float4 v_c0 = cla4[cbase];
    float4 v_c1 = cla4[cbase + HW4];

    int rbase = (b * 4 * A_ + 4 * a) * HW4 + sp4;
    float4 v_tx = reg4[rbase + 0 * HW4];
    float4 v_ty = reg4[rbase + 1 * HW4];
    float4 v_tw = reg4[rbase + 2 * HW4];
    float4 v_th = reg4[rbase + 3 * HW4];

    // Anchor entries: 4 consecutive float4s, lane-consecutive (L1-hot table).
    const float4* tab = d_anc_tab + a * W_ + w0;
    float4 anca[4] = {tab[0], tab[1], tab[2], tab[3]};

    float c0a[4] = {v_c0.x, v_c0.y, v_c0.z, v_c0.w};
    float c1a[4] = {v_c1.x, v_c1.y, v_c1.z, v_c1.w};
    float txa[4] = {v_tx.x, v_tx.y, v_tx.z, v_tx.w};
    float tya[4] = {v_ty.x, v_ty.y, v_ty.z, v_ty.w};
    float twa[4] = {v_tw.x, v_tw.y, v_tw.z, v_tw.w};
    float tha[4] = {v_th.x, v_th.y, v_th.z, v_th.w};

    float4* my = sOut + tid * 9;   // stride 36 words: conflict-free STS.128

    float f[4][9];
    #pragma unroll
    for (int i = 0; i < 4; i++) {
        float acx = anca[i].x, acy = anca[i].y, aw = anca[i].z, ah = anca[i].w;

        float cxn = fmaf(txa[i], aw, acx);
        float cyn = fmaf(tya[i], ah, acy);
        float wvn = expf(twa[i]) * aw;
        float hvn = expf(tha[i]) * ah;

        float ltxn = cxn - 0.5f * wvn;
        float ltyn = cyn - 0.5f * hvn;
        float rbxn = cxn + 0.5f * wvn;
        float rbyn = cyn + 0.5f * hvn;

        // fg > 0.7  <=>  (c1 - c0) > ln(7/3)
        bool valid = ((c1a[i] - c0a[i]) > LOGIT_THRESH)
                     && (ltxn >= 0.0f) && (ltyn >= 0.0f)
                     && (rbxn <= 1.0f) && (rbyn <= 1.0f);
        float m = valid ? 1.0f : 0.0f;

        f[i][0] = (ltxn * S_) * m;
        f[i][1] = (ltyn * S_) * m;
        f[i][2] = (rbxn * S_) * m;
        f[i][3] = (rbyn * S_) * m;
        f[i][4] = cxn * m;
        f[i][5] = cyn * m;
        f[i][6] = wvn * m;
        f[i][7] = hvn * m;
        f[i][8] = m;
    }

    // Pack 4x9 floats into 9 float4 smem slots (output-linear order).
    my[0] = make_float4(f[0][0], f[0][1], f[0][2], f[0][3]);
    my[1] = make_float4(f[0][4], f[0][5], f[0][6], f[0][7]);
    my[2] = make_float4(f[0][8], f[1][0], f[1][1], f[1][2]);
    my[3] = make_float4(f[1][3], f[1][4], f[1][5], f[1][6]);
    my[4] = make_float4(f[1][7], f[1][8], f[2][0], f[2][1]);
    my[5] = make_float4(f[2][2], f[2][3], f[2][4], f[2][5]);
    my[6] = make_float4(f[2][6], f[2][7], f[2][8], f[3][0]);
    my[7] = make_float4(f[3][1], f[3][2], f[3][3], f[3][4]);
    my[8] = make_float4(f[3][5], f[3][6], f[3][7], f[3][8]);

    // Per-warp TMA store: no block barrier.
    int warp = tid >> 5;
    int lane = tid & 31;
    __syncwarp();
    if (lane == 0) {
        // order this warp's STS (visible after syncwarp) to the async proxy
        asm volatile("fence.proxy.async.shared::cta;" ::: "memory");
        uint32_t src = smem_u32(sOut + warp * (32 * 9));
        float* dst = out + (size_t)blockIdx.x * (TPB * 36) + warp * (32 * 36);
        asm volatile(
            "cp.async.bulk.global.shared::cta.bulk_group [%0], [%1], %2;"
            :: "l"(dst), "r"(src), "r"((int)WARP_BYTES) : "memory");
        asm volatile("cp.async.bulk.commit_group;" ::: "memory");
        // hold smem alive until the TMA engine has READ this warp's region
        asm volatile("cp.async.bulk.wait_group.read 0;" ::: "memory");
    }
}

extern "C" void kernel_launch(void* const* d_in, const int* in_sizes, int n_in,
                              void* d_out, int out_size) {
    const float* cla    = (const float*)d_in[0];
    const float* reg    = (const float*)d_in[1];
    const float* anchor = (const float*)d_in[2];
    float* out = (float*)d_out;

    build_anchor_tab<<<(A_ * W_ + 127) / 128, 128>>>(anchor);

    int total_vec = B_ * A_ * H_ * (W_ / 4);   // 589824
    proposal_kernel<<<total_vec / TPB, TPB>>>(cla, reg, out);
}

// round 12
// speedup vs baseline: 1.0535x; 1.0535x over previous
#include <cuda_runtime.h>
#include <cstdint>

// Problem constants (fixed by setup_inputs)
#define B_ 16
#define A_ 9
#define H_ 128
#define W_ 128
#define S_ 2048.0f
// sigmoid(d) > 0.7  <=>  d > ln(7/3)
#define LOGIT_THRESH 0.84729786038720363f

#define TPB 128
#define BLK_BYTES (TPB * 9 * 16)   // 18432 B contiguous output per block

// Anchor table, (a, w) order: (acx, acy, aw, ah). 18 KB, L1/L2-hot.
// Built by block 0 of the SAME kernel (fused prologue); other blocks
// spin briefly on d_flag. d_flag/d_done are self-cleaning across launches:
// the last block to finish wraps the counter and resets the flag, so every
// graph replay performs identical work (no host-side reset needed).
__device__ float4 d_anc_tab[A_ * W_];
__device__ unsigned d_flag = 0;   // 1 = table ready
__device__ unsigned d_done = 0;   // block completion counter (wraps to 0)

__device__ __forceinline__ uint32_t smem_u32(const void* p) {
    uint32_t a;
    asm("{ .reg .u64 t; cvta.to.shared.u64 t, %1; cvt.u32.u64 %0, t; }"
        : "=r"(a) : "l"(p));
    return a;
}

__global__ __launch_bounds__(TPB) void proposal_kernel(
    const float* __restrict__ cla,
    const float* __restrict__ reg,
    const float* __restrict__ anchor,
    float* __restrict__ out)
{
    // Output staging: TPB threads x 9 float4 slots, output-linear layout.
    __shared__ __align__(128) float4 sOut[TPB * 9];   // 18432 B

    const int WQ  = W_ / 4;         // 32
    const int HW4 = (H_ * W_) / 4;  // 4096 float4 per channel plane

    int tid = threadIdx.x;
    int t = blockIdx.x * TPB + tid;
    int wq = t & (WQ - 1);                    // == tid & 31
    int h  = (t / WQ) & (H_ - 1);
    int a  = (t / (WQ * H_)) % A_;            // uniform within a block
    int b  =  t / (WQ * H_ * A_);
    int w0 = wq * 4;

    int sp4 = (h * W_ + w0) >> 2;

    const float4* cla4 = (const float4*)cla;
    const float4* reg4 = (const float4*)reg;

    // ---- issue all input loads FIRST (overlap their latency with the
    //      table-build / spin below) ----
    int cbase = (b * 2 * A_ + 2 * a) * HW4 + sp4;
    float4 v_c0 = cla4[cbase];
    float4 v_c1 = cla4[cbase + HW4];

    int rbase = (b * 4 * A_ + 4 * a) * HW4 + sp4;
    float4 v_tx = reg4[rbase + 0 * HW4];
    float4 v_ty = reg4[rbase + 1 * HW4];
    float4 v_tw = reg4[rbase + 2 * HW4];
    float4 v_th = reg4[rbase + 3 * HW4];

    // ---- fused prologue: block 0 builds the table, everyone else waits ----
    if (blockIdx.x == 0) {
        #pragma unroll
        for (int k = tid; k < A_ * W_; k += TPB) {   // 9 rows per thread
            int aa = k / W_;
            int ww = k - aa * W_;
            long row = (long)aa * ww * (W_ + 1);     // idx[a,w] = a*w*(W+1)
            const float* p = anchor + row * 6;
            float2 acxy = *(const float2*)(p + 2);   // 8B-aligned
            float2 awh  = *(const float2*)(p + 4);
            d_anc_tab[k] = make_float4(acxy.x, acxy.y, awh.x, awh.y);
        }
        __threadfence();
        __syncthreads();
        if (tid == 0) atomicExch(&d_flag, 1u);       // release
    } else {
        if (tid == 0) {
            unsigned v;
            do {
                asm volatile("ld.global.acquire.gpu.u32 %0, [%1];"
                             : "=r"(v) : "l"(&d_flag) : "memory");
                if (!v) __nanosleep(256);
            } while (!v);
        }
        __syncthreads();                              // broadcast readiness
    }

    // Anchor entries: 4 consecutive float4s, lane-consecutive (L1-hot table).
    const float4* tab = d_anc_tab + a * W_ + w0;
    float4 anca[4] = {tab[0], tab[1], tab[2], tab[3]};

    float c0a[4] = {v_c0.x, v_c0.y, v_c0.z, v_c0.w};
    float c1a[4] = {v_c1.x, v_c1.y, v_c1.z, v_c1.w};
    float txa[4] = {v_tx.x, v_tx.y, v_tx.z, v_tx.w};
    float tya[4] = {v_ty.x, v_ty.y, v_ty.z, v_ty.w};
    float twa[4] = {v_tw.x, v_tw.y, v_tw.z, v_tw.w};
    float tha[4] = {v_th.x, v_th.y, v_th.z, v_th.w};

    float4* my = sOut + tid * 9;   // stride 36 words: conflict-free STS.128

    float f[4][9];
    #pragma unroll
    for (int i = 0; i < 4; i++) {
        float acx = anca[i].x, acy = anca[i].y, aw = anca[i].z, ah = anca[i].w;

        float cxn = fmaf(txa[i], aw, acx);
        float cyn = fmaf(tya[i], ah, acy);
        float wvn = expf(twa[i]) * aw;
        float hvn = expf(tha[i]) * ah;

        float ltxn = cxn - 0.5f * wvn;
        float ltyn = cyn - 0.5f * hvn;
        float rbxn = cxn + 0.5f * wvn;
        float rbyn = cyn + 0.5f * hvn;

        // fg > 0.7  <=>  (c1 - c0) > ln(7/3)
        bool valid = ((c1a[i] - c0a[i]) > LOGIT_THRESH)
                     && (ltxn >= 0.0f) && (ltyn >= 0.0f)
                     && (rbxn <= 1.0f) && (rbyn <= 1.0f);
        float m = valid ? 1.0f : 0.0f;

        f[i][0] = (ltxn * S_) * m;
        f[i][1] = (ltyn * S_) * m;
        f[i][2] = (rbxn * S_) * m;
        f[i][3] = (rbyn * S_) * m;
        f[i][4] = cxn * m;
        f[i][5] = cyn * m;
        f[i][6] = wvn * m;
        f[i][7] = hvn * m;
        f[i][8] = m;
    }

    // Pack 4x9 floats into 9 float4 smem slots (output-linear order).
    my[0] = make_float4(f[0][0], f[0][1], f[0][2], f[0][3]);
    my[1] = make_float4(f[0][4], f[0][5], f[0][6], f[0][7]);
    my[2] = make_float4(f[0][8], f[1][0], f[1][1], f[1][2]);
    my[3] = make_float4(f[1][3], f[1][4], f[1][5], f[1][6]);
    my[4] = make_float4(f[1][7], f[1][8], f[2][0], f[2][1]);
    my[5] = make_float4(f[2][2], f[2][3], f[2][4], f[2][5]);
    my[6] = make_float4(f[2][6], f[2][7], f[2][8], f[3][0]);
    my[7] = make_float4(f[3][1], f[3][2], f[3][3], f[3][4]);
    my[8] = make_float4(f[3][5], f[3][6], f[3][7], f[3][8]);

    __syncthreads();

    // Single TMA 1-D bulk store of the block's contiguous 18432B output.
    if (tid == 0) {
        asm volatile("fence.proxy.async.shared::cta;" ::: "memory");
        uint32_t src = smem_u32(sOut);
        float* dst = out + (size_t)blockIdx.x * (TPB * 36);
        asm volatile(
            "cp.async.bulk.global.shared::cta.bulk_group [%0], [%1], %2;"
            :: "l"(dst), "r"(src), "r"((int)BLK_BYTES) : "memory");
        asm volatile("cp.async.bulk.commit_group;" ::: "memory");
        asm volatile("cp.async.bulk.wait_group.read 0;" ::: "memory");

        // Self-cleaning reset: the last block to finish wraps d_done to 0
        // and clears d_flag, so the next graph replay does identical work.
        unsigned old = atomicInc(&d_done, gridDim.x - 1);
        if (old == gridDim.x - 1) atomicExch(&d_flag, 0u);
    }
}

extern "C" void kernel_launch(void* const* d_in, const int* in_sizes, int n_in,
                              void* d_out, int out_size) {
    const float* cla    = (const float*)d_in[0];
    const float* reg    = (const float*)d_in[1];
    const float* anchor = (const float*)d_in[2];
    float* out = (float*)d_out;

    int total_vec = B_ * A_ * H_ * (W_ / 4);   // 589824
    proposal_kernel<<<total_vec / TPB, TPB>>>(cla, reg, anchor, out);
}